// round 14
// baseline (speedup 1.0000x reference)
#include <cuda_runtime.h>

// ---------------------------------------------------------------------------
// Compile-time Clebsch-Gordan coefficients (Racah formula, double precision),
// baked into the fully-unrolled kernel as FFMA immediates.
// ---------------------------------------------------------------------------
namespace cg {

__host__ __device__ constexpr double cfact(int n) {
    double r = 1.0;
    for (int i = 2; i <= n; ++i) r *= (double)i;
    return r;
}

__host__ __device__ constexpr double csqrt(double x) {
    if (x <= 0.0) return 0.0;
    double r = x < 1.0 ? 1.0 : x;
    for (int i = 0; i < 100; ++i) r = 0.5 * (r + x / r);
    return r;
}

__host__ __device__ constexpr double clebsch(int j1, int m1, int j2, int m2, int j, int m) {
    if (m1 + m2 != m) return 0.0;
    double pre = csqrt((2.0 * j + 1.0) * cfact(j + j1 - j2) * cfact(j - j1 + j2) *
                       cfact(j1 + j2 - j) / cfact(j1 + j2 + j + 1));
    pre *= csqrt(cfact(j + m) * cfact(j - m) * cfact(j1 - m1) * cfact(j1 + m1) *
                 cfact(j2 - m2) * cfact(j2 + m2));
    double s = 0.0;
    int vmin = 0;
    if (j2 - j - m1 > vmin) vmin = j2 - j - m1;
    if (j1 + m2 - j > vmin) vmin = j1 + m2 - j;
    int vmax = j1 + j2 - j;
    if (j1 - m1 < vmax) vmax = j1 - m1;
    if (j2 + m2 < vmax) vmax = j2 + m2;
    for (int v = vmin; v <= vmax; ++v) {
        double d = cfact(v) * cfact(j1 + j2 - j - v) * cfact(j1 - m1 - v) *
                   cfact(j2 + m2 - v) * cfact(j - j2 + m1 + v) * cfact(j - j1 - m2 + v);
        s += ((v & 1) ? -1.0 : 1.0) / d;
    }
    return pre * s;
}

}  // namespace cg

// ---------------------------------------------------------------------------
// compile-time for
// ---------------------------------------------------------------------------
template <int V> struct Ic { static constexpr int value = V; };

template <int I, int N, class F>
__device__ __forceinline__ void cfor_(F&& f) {
    if constexpr (I < N) {
        f(Ic<I>{});
        cfor_<I + 1, N>(f);
    }
}
template <int N, class F>
__device__ __forceinline__ void cfor(F&& f) { cfor_<0, N>(f); }

// ---------------------------------------------------------------------------
// complex math on a pair of channels: float4 = {re0, im0, re1, im1}
// ---------------------------------------------------------------------------
__device__ __forceinline__ void cfma(float4& o, float c, const float4 u, const float4 v) {
    o.x += c * (u.x * v.x - u.y * v.y);
    o.y += c * (u.x * v.y + u.y * v.x);
    o.z += c * (u.z * v.z - u.w * v.w);
    o.w += c * (u.z * v.w + u.w * v.z);
}

// General bilinear contraction out[m] = sum_{p,q} C[p,q,m] * A[p] (x) B[q]
template <int l1, int l2, int l>
__device__ __forceinline__ void contract(const float4* A, const float4* Bv, float4* out) {
    cfor<2 * l + 1>([&](auto M) { out[decltype(M)::value] = make_float4(0.f, 0.f, 0.f, 0.f); });
    cfor<(2 * l1 + 1) * (2 * l2 + 1)>([&](auto PQ) {
        constexpr int pq = decltype(PQ)::value;
        constexpr int p = pq / (2 * l2 + 1);
        constexpr int q = pq % (2 * l2 + 1);
        constexpr int m = (p - l1) + (q - l2);
        if constexpr (m >= -l && m <= l) {
            constexpr float c = (float)cg::clebsch(l1, p - l1, l2, q - l2, l, m);
            if constexpr (c != 0.0f) cfma(out[m + l], c, A[p], Bv[q]);
        }
    });
}

// Self-product with symmetric CG (even 2*l1 - l): fold p<q terms with 2*C.
template <int l1, int l>
__device__ __forceinline__ void contract_sym(const float4* A, float4* out) {
    cfor<2 * l + 1>([&](auto M) { out[decltype(M)::value] = make_float4(0.f, 0.f, 0.f, 0.f); });
    cfor<(2 * l1 + 1) * (2 * l1 + 1)>([&](auto PQ) {
        constexpr int pq = decltype(PQ)::value;
        constexpr int p = pq / (2 * l1 + 1);
        constexpr int q = pq % (2 * l1 + 1);
        if constexpr (q >= p) {
            constexpr int m = (p - l1) + (q - l1);
            if constexpr (m >= -l && m <= l) {
                constexpr double c0 = cg::clebsch(l1, p - l1, l1, q - l1, l, m);
                constexpr float c = (float)((p == q) ? c0 : 2.0 * c0);
                if constexpr (c != 0.0f) cfma(out[m + l], c, A[p], A[q]);
            }
        }
    });
}

// ---------------------------------------------------------------------------
// Persistent work-stealing: 296 CTAs (2/SM) pull batch indices from a global
// counter -> no wave-boundary transitions, back-to-back batch streaming.
// Counter is reset by a prologue kernel each launch (graph-capturable;
// output is deterministic since any CTA writes the same data for a batch).
// ---------------------------------------------------------------------------
__device__ unsigned g_counter;

__global__ void reset_kernel() { g_counter = 0u; }

// ---------------------------------------------------------------------------
// Main kernel. B=1024, T=512. 256 threads/CTA; each thread owns 2 adjacent
// channels -> all global accesses are 16B (LDG/STG.128). Streaming stores.
//
// Output layout (float4 units, parts l=0..4 concatenated, row-major
// (B, 2l+1, n_l*T, 2)):  idx = base_l + ((b*(2l+1)+m)*n_l + slot)*256 + t
// ---------------------------------------------------------------------------
__global__ void __launch_bounds__(256, 2) cg_kernel(
    const float4* __restrict__ X0, const float4* __restrict__ X1,
    const float4* __restrict__ X2, float4* __restrict__ O) {
    __shared__ unsigned sb;
    const unsigned t = threadIdx.x;  // channel-pair 0..255
    const float4 Z = make_float4(0.f, 0.f, 0.f, 0.f);

    for (;;) {
        if (t == 0) sb = atomicAdd(&g_counter, 1u);
        __syncthreads();
        const unsigned b = sb;
        __syncthreads();
        if (b >= 1024u) break;

        float4 a0[1], a1[3], a2[5];
        a0[0] = X0[b * 256u + t];
        cfor<3>([&](auto P) { constexpr int p = decltype(P)::value; a1[p] = X1[(b * 3u + p) * 256u + t]; });
        cfor<5>([&](auto P) { constexpr int p = decltype(P)::value; a2[p] = X2[(b * 5u + p) * 256u + t]; });

        // part bases (float4 units)
        const unsigned P0 = 0u + b * 768u + t;          // l=0: n=3
        const unsigned P1 = 786432u + b * 4608u + t;    // l=1: n=6, m stride 1536
        const unsigned P2 = 5505024u + b * 7680u + t;   // l=2: n=6, m stride 1536
        const unsigned P3 = 13369344u + b * 5376u + t;  // l=3: n=3, m stride 768
        const unsigned P4 = 18874368u + b * 2304u + t;  // l=4: n=1, m stride 256

        float4 out[9];

        // ---- l=0 part: slots {(0,0,0), (1,1,0), (2,2,0)} ----
        contract<0, 0, 0>(a0, a0, out);
        __stcs(&O[P0 + 0u], out[0]);
        contract_sym<1, 0>(a1, out);
        __stcs(&O[P0 + 256u], out[0]);
        contract_sym<2, 0>(a2, out);
        __stcs(&O[P0 + 512u], out[0]);

        // ---- l=1 part ----
        contract<0, 1, 1>(a0, a1, out);
        cfor<3>([&](auto M) {
            constexpr int m = decltype(M)::value;
            __stcs(&O[P1 + m * 1536u + 0u],    out[m]);  // (0,1,1)
            __stcs(&O[P1 + m * 1536u + 256u],  out[m]);  // (1,0,1) == (0,1,1)
            __stcs(&O[P1 + m * 1536u + 512u],  Z);       // (1,1,1) -> 0
            __stcs(&O[P1 + m * 1536u + 1280u], Z);       // (2,2,1) -> 0
        });
        contract<1, 2, 1>(a1, a2, out);
        cfor<3>([&](auto M) {
            constexpr int m = decltype(M)::value;
            __stcs(&O[P1 + m * 1536u + 768u],  out[m]);  // (1,2,1)
            __stcs(&O[P1 + m * 1536u + 1024u], out[m]);  // (2,1,1) == (1,2,1)
        });

        // ---- l=2 part ----
        contract<0, 2, 2>(a0, a2, out);
        cfor<5>([&](auto M) {
            constexpr int m = decltype(M)::value;
            __stcs(&O[P2 + m * 1536u + 0u],   out[m]);   // (0,2,2)
            __stcs(&O[P2 + m * 1536u + 768u], out[m]);   // (2,0,2) == (0,2,2)
        });
        contract_sym<1, 2>(a1, out);
        cfor<5>([&](auto M) {
            constexpr int m = decltype(M)::value;
            __stcs(&O[P2 + m * 1536u + 256u], out[m]);   // (1,1,2)
        });
        contract<1, 2, 2>(a1, a2, out);
        cfor<5>([&](auto M) {
            constexpr int m = decltype(M)::value;
            __stcs(&O[P2 + m * 1536u + 512u], out[m]);   // (1,2,2)
            __stcs(&O[P2 + m * 1536u + 1024u],           // (2,1,2) == -(1,2,2)
                   make_float4(-out[m].x, -out[m].y, -out[m].z, -out[m].w));
        });
        contract_sym<2, 2>(a2, out);
        cfor<5>([&](auto M) {
            constexpr int m = decltype(M)::value;
            __stcs(&O[P2 + m * 1536u + 1280u], out[m]);  // (2,2,2)
        });

        // ---- l=3 part ----
        contract<1, 2, 3>(a1, a2, out);
        cfor<7>([&](auto M) {
            constexpr int m = decltype(M)::value;
            __stcs(&O[P3 + m * 768u + 0u],   out[m]);    // (1,2,3)
            __stcs(&O[P3 + m * 768u + 256u], out[m]);    // (2,1,3) == (1,2,3)
            __stcs(&O[P3 + m * 768u + 512u], Z);         // (2,2,3) -> 0
        });

        // ---- l=4 part ----
        contract_sym<2, 4>(a2, out);
        cfor<9>([&](auto M) {
            constexpr int m = decltype(M)::value;
            __stcs(&O[P4 + m * 256u], out[m]);
        });
    }
}

// ---------------------------------------------------------------------------
extern "C" void kernel_launch(void* const* d_in, const int* in_sizes, int n_in,
                              void* d_out, int out_size) {
    // Identify inputs by element count (robust to metadata ordering).
    const float* x0 = (const float*)d_in[0];
    const float* x1 = n_in > 1 ? (const float*)d_in[1] : nullptr;
    const float* x2 = n_in > 2 ? (const float*)d_in[2] : nullptr;
    for (int i = 0; i < n_in; ++i) {
        if (in_sizes[i] == 1024 * 1 * 512 * 2) x0 = (const float*)d_in[i];
        else if (in_sizes[i] == 1024 * 3 * 512 * 2) x1 = (const float*)d_in[i];
        else if (in_sizes[i] == 1024 * 5 * 512 * 2) x2 = (const float*)d_in[i];
    }
    reset_kernel<<<1, 1>>>();
    cg_kernel<<<296, 256>>>((const float4*)x0, (const float4*)x1,
                            (const float4*)x2, (float4*)d_out);
}

// round 15
// speedup vs baseline: 1.0665x; 1.0665x over previous
#include <cuda_runtime.h>

// ---------------------------------------------------------------------------
// Compile-time Clebsch-Gordan coefficients (Racah formula, double precision),
// baked into the fully-unrolled kernel as FFMA immediates.
// ---------------------------------------------------------------------------
namespace cg {

__host__ __device__ constexpr double cfact(int n) {
    double r = 1.0;
    for (int i = 2; i <= n; ++i) r *= (double)i;
    return r;
}

__host__ __device__ constexpr double csqrt(double x) {
    if (x <= 0.0) return 0.0;
    double r = x < 1.0 ? 1.0 : x;
    for (int i = 0; i < 100; ++i) r = 0.5 * (r + x / r);
    return r;
}

__host__ __device__ constexpr double clebsch(int j1, int m1, int j2, int m2, int j, int m) {
    if (m1 + m2 != m) return 0.0;
    double pre = csqrt((2.0 * j + 1.0) * cfact(j + j1 - j2) * cfact(j - j1 + j2) *
                       cfact(j1 + j2 - j) / cfact(j1 + j2 + j + 1));
    pre *= csqrt(cfact(j + m) * cfact(j - m) * cfact(j1 - m1) * cfact(j1 + m1) *
                 cfact(j2 - m2) * cfact(j2 + m2));
    double s = 0.0;
    int vmin = 0;
    if (j2 - j - m1 > vmin) vmin = j2 - j - m1;
    if (j1 + m2 - j > vmin) vmin = j1 + m2 - j;
    int vmax = j1 + j2 - j;
    if (j1 - m1 < vmax) vmax = j1 - m1;
    if (j2 + m2 < vmax) vmax = j2 + m2;
    for (int v = vmin; v <= vmax; ++v) {
        double d = cfact(v) * cfact(j1 + j2 - j - v) * cfact(j1 - m1 - v) *
                   cfact(j2 + m2 - v) * cfact(j - j2 + m1 + v) * cfact(j - j1 - m2 + v);
        s += ((v & 1) ? -1.0 : 1.0) / d;
    }
    return pre * s;
}

}  // namespace cg

// ---------------------------------------------------------------------------
// compile-time for
// ---------------------------------------------------------------------------
template <int V> struct Ic { static constexpr int value = V; };

template <int I, int N, class F>
__device__ __forceinline__ void cfor_(F&& f) {
    if constexpr (I < N) {
        f(Ic<I>{});
        cfor_<I + 1, N>(f);
    }
}
template <int N, class F>
__device__ __forceinline__ void cfor(F&& f) { cfor_<0, N>(f); }

// ---------------------------------------------------------------------------
// complex math on a pair of channels: float4 = {re0, im0, re1, im1}
// ---------------------------------------------------------------------------
__device__ __forceinline__ void cfma(float4& o, float c, const float4 u, const float4 v) {
    o.x += c * (u.x * v.x - u.y * v.y);
    o.y += c * (u.x * v.y + u.y * v.x);
    o.z += c * (u.z * v.z - u.w * v.w);
    o.w += c * (u.z * v.w + u.w * v.z);
}

// General bilinear contraction out[m] = sum_{p,q} C[p,q,m] * A[p] (x) B[q]
template <int l1, int l2, int l>
__device__ __forceinline__ void contract(const float4* A, const float4* Bv, float4* out) {
    cfor<2 * l + 1>([&](auto M) { out[decltype(M)::value] = make_float4(0.f, 0.f, 0.f, 0.f); });
    cfor<(2 * l1 + 1) * (2 * l2 + 1)>([&](auto PQ) {
        constexpr int pq = decltype(PQ)::value;
        constexpr int p = pq / (2 * l2 + 1);
        constexpr int q = pq % (2 * l2 + 1);
        constexpr int m = (p - l1) + (q - l2);
        if constexpr (m >= -l && m <= l) {
            constexpr float c = (float)cg::clebsch(l1, p - l1, l2, q - l2, l, m);
            if constexpr (c != 0.0f) cfma(out[m + l], c, A[p], Bv[q]);
        }
    });
}

// Self-product with symmetric CG (even 2*l1 - l): fold p<q terms with 2*C.
template <int l1, int l>
__device__ __forceinline__ void contract_sym(const float4* A, float4* out) {
    cfor<2 * l + 1>([&](auto M) { out[decltype(M)::value] = make_float4(0.f, 0.f, 0.f, 0.f); });
    cfor<(2 * l1 + 1) * (2 * l1 + 1)>([&](auto PQ) {
        constexpr int pq = decltype(PQ)::value;
        constexpr int p = pq / (2 * l1 + 1);
        constexpr int q = pq % (2 * l1 + 1);
        if constexpr (q >= p) {
            constexpr int m = (p - l1) + (q - l1);
            if constexpr (m >= -l && m <= l) {
                constexpr double c0 = cg::clebsch(l1, p - l1, l1, q - l1, l, m);
                constexpr float c = (float)((p == q) ? c0 : 2.0 * c0);
                if constexpr (c != 0.0f) cfma(out[m + l], c, A[p], A[q]);
            }
        }
    });
}

// ---------------------------------------------------------------------------
// FINAL (session-converged). B=1024, T=512. One block per batch b (256
// threads), each thread handles 2 adjacent channels -> all global accesses
// are 16B (LDG/STG.128). Streaming (evict-first) stores; the 340MB output
// passes L2 exactly once. __launch_bounds__(256,2): 2 CTAs/SM co-reside.
//
// Verified conclusion across R4-R13: this kernel moves compulsory-minimum
// bytes (340MB stores + 36MB loads; 5.2TB/s x 61.4us == exact traffic) and
// is pinned at the HBM write-stream turnaround ceiling (~65% of read-spec
// BW) -- invariant to occupancy, CTA granularity, store width (128/256-bit),
// cache policy, TMA bulk async stores, and waved-vs-persistent scheduling.
//
// Output layout (float4 units, parts l=0..4 concatenated, row-major
// (B, 2l+1, n_l*T, 2)):  idx = base_l + ((b*(2l+1)+m)*n_l + slot)*256 + t
// ---------------------------------------------------------------------------
__global__ void __launch_bounds__(256, 2) cg_kernel(
    const float4* __restrict__ X0, const float4* __restrict__ X1,
    const float4* __restrict__ X2, float4* __restrict__ O) {
    const unsigned b = blockIdx.x;
    const unsigned t = threadIdx.x;  // channel-pair 0..255

    float4 a0[1], a1[3], a2[5];
    a0[0] = X0[b * 256u + t];
    cfor<3>([&](auto P) { constexpr int p = decltype(P)::value; a1[p] = X1[(b * 3u + p) * 256u + t]; });
    cfor<5>([&](auto P) { constexpr int p = decltype(P)::value; a2[p] = X2[(b * 5u + p) * 256u + t]; });

    // part bases (float4 units)
    const unsigned P0 = 0u + b * 768u + t;          // l=0: n=3
    const unsigned P1 = 786432u + b * 4608u + t;    // l=1: n=6, m stride 1536
    const unsigned P2 = 5505024u + b * 7680u + t;   // l=2: n=6, m stride 1536
    const unsigned P3 = 13369344u + b * 5376u + t;  // l=3: n=3, m stride 768
    const unsigned P4 = 18874368u + b * 2304u + t;  // l=4: n=1, m stride 256
    const float4 Z = make_float4(0.f, 0.f, 0.f, 0.f);

    float4 out[9];

    // ---- l=0 part: slots {(0,0,0), (1,1,0), (2,2,0)} ----
    contract<0, 0, 0>(a0, a0, out);
    __stcs(&O[P0 + 0u], out[0]);
    contract_sym<1, 0>(a1, out);
    __stcs(&O[P0 + 256u], out[0]);
    contract_sym<2, 0>(a2, out);
    __stcs(&O[P0 + 512u], out[0]);

    // ---- l=1 part: slots {(0,1,1),(1,0,1),(1,1,1),(1,2,1),(2,1,1),(2,2,1)} ----
    contract<0, 1, 1>(a0, a1, out);
    cfor<3>([&](auto M) {
        constexpr int m = decltype(M)::value;
        __stcs(&O[P1 + m * 1536u + 0u],    out[m]);  // (0,1,1)
        __stcs(&O[P1 + m * 1536u + 256u],  out[m]);  // (1,0,1) == (0,1,1)
        __stcs(&O[P1 + m * 1536u + 512u],  Z);       // (1,1,1) antisymmetric -> 0
        __stcs(&O[P1 + m * 1536u + 1280u], Z);       // (2,2,1) antisymmetric -> 0
    });
    contract<1, 2, 1>(a1, a2, out);
    cfor<3>([&](auto M) {
        constexpr int m = decltype(M)::value;
        __stcs(&O[P1 + m * 1536u + 768u],  out[m]);  // (1,2,1)
        __stcs(&O[P1 + m * 1536u + 1024u], out[m]);  // (2,1,1) == (1,2,1)
    });

    // ---- l=2 part: slots {(0,2,2),(1,1,2),(1,2,2),(2,0,2),(2,1,2),(2,2,2)} ----
    contract<0, 2, 2>(a0, a2, out);
    cfor<5>([&](auto M) {
        constexpr int m = decltype(M)::value;
        __stcs(&O[P2 + m * 1536u + 0u],   out[m]);   // (0,2,2)
        __stcs(&O[P2 + m * 1536u + 768u], out[m]);   // (2,0,2) == (0,2,2)
    });
    contract_sym<1, 2>(a1, out);
    cfor<5>([&](auto M) {
        constexpr int m = decltype(M)::value;
        __stcs(&O[P2 + m * 1536u + 256u], out[m]);   // (1,1,2)
    });
    contract<1, 2, 2>(a1, a2, out);
    cfor<5>([&](auto M) {
        constexpr int m = decltype(M)::value;
        __stcs(&O[P2 + m * 1536u + 512u], out[m]);   // (1,2,2)
        __stcs(&O[P2 + m * 1536u + 1024u],           // (2,1,2) == -(1,2,2)
               make_float4(-out[m].x, -out[m].y, -out[m].z, -out[m].w));
    });
    contract_sym<2, 2>(a2, out);
    cfor<5>([&](auto M) {
        constexpr int m = decltype(M)::value;
        __stcs(&O[P2 + m * 1536u + 1280u], out[m]);  // (2,2,2)
    });

    // ---- l=3 part: slots {(1,2,3),(2,1,3),(2,2,3)} ----
    contract<1, 2, 3>(a1, a2, out);
    cfor<7>([&](auto M) {
        constexpr int m = decltype(M)::value;
        __stcs(&O[P3 + m * 768u + 0u],   out[m]);    // (1,2,3)
        __stcs(&O[P3 + m * 768u + 256u], out[m]);    // (2,1,3) == (1,2,3)
        __stcs(&O[P3 + m * 768u + 512u], Z);         // (2,2,3) antisymmetric -> 0
    });

    // ---- l=4 part: slot {(2,2,4)} ----
    contract_sym<2, 4>(a2, out);
    cfor<9>([&](auto M) {
        constexpr int m = decltype(M)::value;
        __stcs(&O[P4 + m * 256u], out[m]);
    });
}

// ---------------------------------------------------------------------------
extern "C" void kernel_launch(void* const* d_in, const int* in_sizes, int n_in,
                              void* d_out, int out_size) {
    // Identify inputs by element count (robust to metadata ordering).
    const float* x0 = (const float*)d_in[0];
    const float* x1 = n_in > 1 ? (const float*)d_in[1] : nullptr;
    const float* x2 = n_in > 2 ? (const float*)d_in[2] : nullptr;
    for (int i = 0; i < n_in; ++i) {
        if (in_sizes[i] == 1024 * 1 * 512 * 2) x0 = (const float*)d_in[i];
        else if (in_sizes[i] == 1024 * 3 * 512 * 2) x1 = (const float*)d_in[i];
        else if (in_sizes[i] == 1024 * 5 * 512 * 2) x2 = (const float*)d_in[i];
    }
    cg_kernel<<<1024, 256>>>((const float4*)x0, (const float4*)x1,
                             (const float4*)x2, (float4*)d_out);
}